// round 4
// baseline (speedup 1.0000x reference)
#include <cuda_runtime.h>
#include <math.h>

// Problem constants (fixed by reference setup_inputs)
#define B 32
#define D 64
#define H 192
#define W 128
#define K 64
#define THREADS 512
#define GRID B                 // one CTA per batch
#define ROWPAD 68              // row stride (words): 16B-aligned, conflict-free STS

__device__ float        g_partial[GRID];
__device__ unsigned int g_count = 0;

// packed f32x2 FMA (Blackwell; ptxas never auto-fuses this from C++)
__device__ __forceinline__ unsigned long long ffma2(unsigned long long a,
                                                    unsigned long long b,
                                                    unsigned long long c)
{
    unsigned long long d;
    asm("fma.rn.f32x2 %0, %1, %2, %3;" : "=l"(d) : "l"(a), "l"(b), "l"(c));
    return d;
}
__device__ __forceinline__ float2 unpack2(unsigned long long v)
{
    float x, y;
    asm("mov.b64 {%0, %1}, %2;" : "=f"(x), "=f"(y) : "l"(v));
    return make_float2(x, y);
}

__global__ __launch_bounds__(THREADS, 1)
void tagloss_fused_kernel(const float* __restrict__ ebd,
                          const float* __restrict__ kpts,
                          const int*   __restrict__ tags,
                          float*       __restrict__ out)
{
    const int b   = blockIdx.x;
    const int tid = threadIdx.x;

    __shared__ __align__(16) float erow[K][ROWPAD]; // [k][d], rows 16B-aligned
    __shared__ float snorm[K];
    __shared__ int   sr[K], sc[K], stags[K];
    __shared__ float red[THREADS];
    __shared__ bool  s_last;

    // --- keypoint -> pixel indices + tags ---
    if (tid < K) {
        float r = kpts[((size_t)b * K + tid) * 2 + 0] * (float)H;
        float c = kpts[((size_t)b * K + tid) * 2 + 1] * (float)W;
        sr[tid] = (int)floorf(r);
        sc[tid] = (int)floorf(c);
        stags[tid] = tags[(size_t)b * K + tid];
    }
    __syncthreads();

    // --- gather: 4096 scattered loads, 8 per thread.
    // Lanes take consecutive d (same k): STS conflict-free, LDG scattered anyway.
    const float* eb = ebd + (size_t)b * D * H * W;
    #pragma unroll
    for (int it = 0; it < (K * D) / THREADS; it++) {
        int n = tid + it * THREADS;
        int d = n & 63;
        int k = n >> 6;
        erow[k][d] = eb[(size_t)d * (H * W) + sr[k] * W + sc[k]];
    }
    __syncthreads();

    // --- hoist own column j as packed f32x2 pairs (one-time, from row j) ---
    const int j = tid & 63;
    unsigned long long ejp[D / 2];
    {
        const ulonglong2* myrow = (const ulonglong2*)erow[j];
        #pragma unroll
        for (int d4 = 0; d4 < D / 4; d4++) {
            ulonglong2 t = myrow[d4];
            ejp[2 * d4 + 0] = t.x;
            ejp[2 * d4 + 1] = t.y;
        }
    }

    // --- per-keypoint squared norms (threads 0..63, packed FMA) ---
    if (tid < K) {
        unsigned long long s01 = 0ull, s23 = 0ull;
        const ulonglong2* row = (const ulonglong2*)erow[tid];
        #pragma unroll
        for (int d4 = 0; d4 < D / 4; d4++) {
            ulonglong2 v = row[d4];
            s01 = ffma2(v.x, v.x, s01);
            s23 = ffma2(v.y, v.y, s23);
        }
        float2 a = unpack2(s01), bb = unpack2(s23);
        snorm[tid] = (a.x + a.y) + (bb.x + bb.y);
    }
    __syncthreads();

    const float nj = snorm[j];
    const int   tj = stags[j];

    // --- pairwise loss: 8 i-rows per thread (i = tid>>6 + 8*ig), row broadcast ---
    float acc = 0.0f;
    #pragma unroll
    for (int ig = 0; ig < 8; ig++) {
        const int i = (tid >> 6) + ig * 8;
        const ulonglong2* rowi = (const ulonglong2*)erow[i];  // warp-broadcast
        unsigned long long s01 = 0ull, s23 = 0ull;
        #pragma unroll
        for (int d4 = 0; d4 < D / 4; d4++) {
            ulonglong2 v = rowi[d4];
            s01 = ffma2(v.x, ejp[2 * d4 + 0], s01);
            s23 = ffma2(v.y, ejp[2 * d4 + 1], s23);
        }
        float2 a = unpack2(s01), bb = unpack2(s23);
        float s = (a.x + a.y) + (bb.x + bb.y);

        float expo = (snorm[i] + nj - 2.0f * s) * (1.0f / (float)D);
        float pred = 2.0f / (1.0f + __expf(expo));
        float ts   = (stags[i] == tj) ? 1.0f : 0.0f;
        float dd   = pred - ts;
        acc = fmaf(dd, dd, acc);
    }

    // --- CTA reduction of 512 partials ---
    red[tid] = acc;
    __syncthreads();
    #pragma unroll
    for (int off = 256; off >= 32; off >>= 1) {
        if (tid < off) red[tid] += red[tid + off];
        __syncthreads();
    }
    if (tid < 32) {
        float v = red[tid];
        #pragma unroll
        for (int o = 16; o > 0; o >>= 1)
            v += __shfl_down_sync(0xFFFFFFFFu, v, o);
        if (tid == 0) {
            g_partial[b] = v;
            __threadfence();
            unsigned old = atomicAdd(&g_count, 1u);
            s_last = (old == GRID - 1);
        }
    }
    __syncthreads();

    // --- last CTA: deterministic final reduce over 32 partials ---
    if (s_last && tid < 32) {
        float v = g_partial[tid];
        #pragma unroll
        for (int o = 16; o > 0; o >>= 1)
            v += __shfl_down_sync(0xFFFFFFFFu, v, o);
        if (tid == 0) {
            out[0] = v * (1.0f / (float)(K * K * B));
            g_count = 0;                 // reset for next graph replay
        }
    }
}

extern "C" void kernel_launch(void* const* d_in, const int* in_sizes, int n_in,
                              void* d_out, int out_size)
{
    const float* ebd  = (const float*)d_in[0];   // [32,64,192,128] f32
    const float* kpts = (const float*)d_in[1];   // [32,64,2] f32
    const int*   tags = (const int*)d_in[2];     // [32,64] i32
    float* out = (float*)d_out;

    tagloss_fused_kernel<<<GRID, THREADS>>>(ebd, kpts, tags, out);
}

// round 5
// speedup vs baseline: 1.1335x; 1.1335x over previous
#include <cuda_runtime.h>
#include <math.h>

#define B 32
#define D 64
#define H 192
#define W 128
#define K 64
#define CPB 4                  // CTAs per batch
#define GRID (B * CPB)         // 128 (<= 148 SMs: single wave, co-resident)
#define THREADS 256
#define KPC (K / CPB)          // 16 keypoints gathered / i-rows computed per CTA
#define ROWPAD 68              // SMEM row stride in words (17 x 16B: aligned, conflict-free)

__device__ float        g_E[B][K][D];     // staged embeddings (512 KB, L2-resident)
__device__ float        g_partial[GRID];
__device__ unsigned int g_cnt[B];         // per-batch gather-complete counters
__device__ unsigned int g_done = 0;

// packed f32x2 FMA (ptxas never auto-fuses this from C++)
__device__ __forceinline__ unsigned long long ffma2(unsigned long long a,
                                                    unsigned long long b,
                                                    unsigned long long c)
{
    unsigned long long d;
    asm("fma.rn.f32x2 %0, %1, %2, %3;" : "=l"(d) : "l"(a), "l"(b), "l"(c));
    return d;
}
__device__ __forceinline__ float2 unpack2(unsigned long long v)
{
    float x, y;
    asm("mov.b64 {%0, %1}, %2;" : "=f"(x), "=f"(y) : "l"(v));
    return make_float2(x, y);
}

__global__ __launch_bounds__(THREADS, 1)
void tagloss_fused_kernel(const float* __restrict__ ebd,
                          const float* __restrict__ kpts,
                          const int*   __restrict__ tags,
                          float*       __restrict__ out)
{
    const int cta   = blockIdx.x;
    const int b     = cta >> 2;
    const int chunk = cta & 3;
    const int tid   = threadIdx.x;

    __shared__ int   sr[KPC], sc[KPC];
    __shared__ __align__(16) float erow[K][ROWPAD];
    __shared__ float snorm[K];
    __shared__ int   stags[K];
    __shared__ float red[THREADS];
    __shared__ bool  s_last;

    // ---- phase 1: indices for this CTA's 16 keypoints ----
    if (tid < KPC) {
        int kk = chunk * KPC + tid;
        float r = kpts[((size_t)b * K + kk) * 2 + 0] * (float)H;
        float c = kpts[((size_t)b * K + kk) * 2 + 1] * (float)W;
        sr[tid] = (int)floorf(r);
        sc[tid] = (int)floorf(c);
    }
    __syncthreads();

    // ---- gather 1024 scattered elements; coalesced STG into g_E ----
    {
        const float* eb = ebd + (size_t)b * D * H * W;
        float v[4];
        #pragma unroll
        for (int it = 0; it < 4; it++) {            // 4*256 = 1024
            int n  = tid + it * THREADS;
            int d  = n & 63;
            int kl = n >> 6;
            v[it] = eb[(size_t)d * (H * W) + sr[kl] * W + sc[kl]];
        }
        #pragma unroll
        for (int it = 0; it < 4; it++) {
            int n  = tid + it * THREADS;
            int d  = n & 63;
            int kk = chunk * KPC + (n >> 6);
            g_E[b][kk][d] = v[it];                  // consecutive d: 128B coalesced
        }
    }
    __syncthreads();

    // ---- per-batch sync: wait until all 4 quarter-gathers of batch b landed ----
    if (tid == 0) {
        __threadfence();                            // release E stores
        atomicAdd(&g_cnt[b], 1u);
        while (((volatile unsigned int*)g_cnt)[b] < CPB) { }
        __threadfence();                            // acquire
    }
    __syncthreads();

    // ---- phase 2: load full batch E (16 KB) coalesced into SMEM ----
    #pragma unroll
    for (int it = 0; it < (K * D / 4) / THREADS; it++) {   // 4 float4 per thread
        int idx = tid + it * THREADS;
        int kk  = idx >> 4;
        int d4  = idx & 15;
        float4 t = ((const float4*)g_E[b][kk])[d4];
        ((float4*)&erow[kk][0])[d4] = t;
    }
    if (tid < K) stags[tid] = tags[(size_t)b * K + tid];
    __syncthreads();

    // ---- hoist own column j packed; norm from registers ----
    const int j = tid & 63;
    unsigned long long ejp[D / 2];
    {
        const ulonglong2* myrow = (const ulonglong2*)erow[j];
        #pragma unroll
        for (int d4 = 0; d4 < D / 4; d4++) {
            ulonglong2 t = myrow[d4];
            ejp[2 * d4 + 0] = t.x;
            ejp[2 * d4 + 1] = t.y;
        }
    }
    {
        unsigned long long s01 = 0ull, s23 = 0ull;
        #pragma unroll
        for (int d4 = 0; d4 < D / 4; d4++) {
            s01 = ffma2(ejp[2 * d4 + 0], ejp[2 * d4 + 0], s01);
            s23 = ffma2(ejp[2 * d4 + 1], ejp[2 * d4 + 1], s23);
        }
        float2 a = unpack2(s01), bb = unpack2(s23);
        if (tid < K) snorm[tid] = (a.x + a.y) + (bb.x + bb.y);
    }
    __syncthreads();

    const float nj = snorm[j];
    const int   tj = stags[j];

    // ---- pairwise loss: 4 i-rows per thread (this CTA's 16-row chunk) ----
    float acc = 0.0f;
    #pragma unroll
    for (int ig = 0; ig < 4; ig++) {
        const int i = chunk * KPC + (tid >> 6) + ig * 4;
        const ulonglong2* rowi = (const ulonglong2*)erow[i];   // warp-broadcast LDS.128
        unsigned long long s01 = 0ull, s23 = 0ull;
        #pragma unroll
        for (int d4 = 0; d4 < D / 4; d4++) {
            ulonglong2 v = rowi[d4];
            s01 = ffma2(v.x, ejp[2 * d4 + 0], s01);
            s23 = ffma2(v.y, ejp[2 * d4 + 1], s23);
        }
        float2 a = unpack2(s01), bb = unpack2(s23);
        float s = (a.x + a.y) + (bb.x + bb.y);

        float expo = (snorm[i] + nj - 2.0f * s) * (1.0f / (float)D);
        float pred = 2.0f / (1.0f + __expf(expo));
        float ts   = (stags[i] == tj) ? 1.0f : 0.0f;
        float dd   = pred - ts;
        acc = fmaf(dd, dd, acc);
    }

    // ---- CTA reduction ----
    red[tid] = acc;
    __syncthreads();
    #pragma unroll
    for (int off = 128; off >= 32; off >>= 1) {
        if (tid < off) red[tid] += red[tid + off];
        __syncthreads();
    }
    if (tid < 32) {
        float v = red[tid];
        #pragma unroll
        for (int o = 16; o > 0; o >>= 1)
            v += __shfl_down_sync(0xFFFFFFFFu, v, o);
        if (tid == 0) {
            g_partial[cta] = v;
            __threadfence();
            unsigned old = atomicAdd(&g_done, 1u);
            s_last = (old == GRID - 1);
        }
    }
    __syncthreads();

    // ---- last CTA: final reduce over 128 partials + reset counters for replay ----
    if (s_last && tid < 32) {
        float v = g_partial[tid]      + g_partial[tid + 32]
                + g_partial[tid + 64] + g_partial[tid + 96];
        #pragma unroll
        for (int o = 16; o > 0; o >>= 1)
            v += __shfl_down_sync(0xFFFFFFFFu, v, o);
        g_cnt[tid] = 0;                  // all 32 batch counters
        if (tid == 0) {
            g_done = 0;
            out[0] = v * (1.0f / (float)(K * K * B));
        }
    }
}

extern "C" void kernel_launch(void* const* d_in, const int* in_sizes, int n_in,
                              void* d_out, int out_size)
{
    const float* ebd  = (const float*)d_in[0];   // [32,64,192,128] f32
    const float* kpts = (const float*)d_in[1];   // [32,64,2] f32
    const int*   tags = (const int*)d_in[2];     // [32,64] i32
    float* out = (float*)d_out;

    tagloss_fused_kernel<<<GRID, THREADS>>>(ebd, kpts, tags, out);
}

// round 6
// speedup vs baseline: 1.1910x; 1.0507x over previous
#include <cuda_runtime.h>
#include <math.h>

#define B 32
#define D 64
#define H 192
#define W 128
#define K 64
#define CPB 4                   // CTAs per batch = cluster size
#define GRID (B * CPB)          // 128 CTAs, 32 clusters of 4 (single wave)
#define THREADS 256
#define KPC (K / CPB)           // 16 keypoints gathered / i-rows per CTA
#define ROWPAD 68               // row stride (words): 16B-aligned

__device__ float        g_partial[GRID];
__device__ unsigned int g_done = 0;

// ---- PTX helpers ----
__device__ __forceinline__ unsigned long long ffma2(unsigned long long a,
                                                    unsigned long long b,
                                                    unsigned long long c)
{
    unsigned long long d;
    asm("fma.rn.f32x2 %0, %1, %2, %3;" : "=l"(d) : "l"(a), "l"(b), "l"(c));
    return d;
}
__device__ __forceinline__ float2 unpack2(unsigned long long v)
{
    float x, y;
    asm("mov.b64 {%0, %1}, %2;" : "=f"(x), "=f"(y) : "l"(v));
    return make_float2(x, y);
}
__device__ __forceinline__ unsigned smem_u32(const void* p)
{
    unsigned a;
    asm("{ .reg .u64 t; cvta.to.shared.u64 t, %1; cvt.u32.u64 %0, t; }"
        : "=r"(a) : "l"(p));
    return a;
}
__device__ __forceinline__ unsigned mapa_u32(unsigned addr, unsigned rank)
{
    unsigned r;
    asm("mapa.shared::cluster.u32 %0, %1, %2;" : "=r"(r) : "r"(addr), "r"(rank));
    return r;
}
__device__ __forceinline__ void st_cluster_f32(unsigned addr, float v)
{
    asm volatile("st.shared::cluster.f32 [%0], %1;" :: "r"(addr), "f"(v) : "memory");
}
__device__ __forceinline__ unsigned ctarank()
{
    unsigned r;
    asm("mov.u32 %0, %%cluster_ctarank;" : "=r"(r));
    return r;
}

__global__ __launch_bounds__(THREADS, 1) __cluster_dims__(CPB, 1, 1)
void tagloss_fused_kernel(const float* __restrict__ ebd,
                          const float* __restrict__ kpts,
                          const int*   __restrict__ tags,
                          float*       __restrict__ out)
{
    const int cta   = blockIdx.x;
    const int b     = cta >> 2;
    const int chunk = (int)ctarank();     // quarter within the batch
    const int tid   = threadIdx.x;

    __shared__ __align__(16) float erow[K][ROWPAD];  // all 64 rows (filled by 4 CTAs)
    __shared__ float snorm[K];
    __shared__ int   sr[KPC], sc[KPC], stags[K];
    __shared__ float swarp[THREADS / 32];
    __shared__ bool  s_last;

    // ---- indices for this CTA's 16 keypoints + all 64 tags ----
    if (tid < KPC) {
        float2 rc = ((const float2*)kpts)[(size_t)b * K + chunk * KPC + tid];
        sr[tid] = (int)floorf(rc.x * (float)H);
        sc[tid] = (int)floorf(rc.y * (float)W);
    }
    if (tid < K) stags[tid] = tags[(size_t)b * K + tid];
    __syncthreads();

    // ---- gather this quarter (1024 scattered loads, 4/thread) ----
    const float* eb = ebd + (size_t)b * D * H * W;
    float gv[4];
    #pragma unroll
    for (int it = 0; it < 4; it++) {
        int n  = tid + it * THREADS;
        int d  = n & 63;                  // lanes: consecutive d
        int kl = n >> 6;                  // local keypoint 0..15
        gv[it] = eb[(size_t)d * (H * W) + sr[kl] * W + sc[kl]];
    }
    // ---- broadcast into all 4 cluster CTAs' SMEM (DSMEM stores) ----
    #pragma unroll
    for (int it = 0; it < 4; it++) {
        int n   = tid + it * THREADS;
        int d   = n & 63;
        int row = chunk * KPC + (n >> 6);
        unsigned laddr = smem_u32(&erow[row][d]);
        #pragma unroll
        for (unsigned r = 0; r < CPB; r++)
            st_cluster_f32(mapa_u32(laddr, r), gv[it]);
    }
    // cluster barrier: arrive has release semantics (orders the DSMEM stores)
    asm volatile("barrier.cluster.arrive.aligned;" ::: "memory");
    asm volatile("barrier.cluster.wait.aligned;"   ::: "memory");

    // ---- hoist own column j (packed f32x2) + norms ----
    const int j = tid & 63;
    unsigned long long ejp[D / 2];
    {
        const ulonglong2* myrow = (const ulonglong2*)erow[j];
        #pragma unroll
        for (int d4 = 0; d4 < D / 4; d4++) {
            ulonglong2 t = myrow[d4];
            ejp[2 * d4 + 0] = t.x;
            ejp[2 * d4 + 1] = t.y;
        }
    }
    {
        unsigned long long s01 = 0ull, s23 = 0ull;
        #pragma unroll
        for (int d4 = 0; d4 < D / 4; d4++) {
            s01 = ffma2(ejp[2 * d4 + 0], ejp[2 * d4 + 0], s01);
            s23 = ffma2(ejp[2 * d4 + 1], ejp[2 * d4 + 1], s23);
        }
        float2 a = unpack2(s01), bb = unpack2(s23);
        if (tid < K) snorm[tid] = (a.x + a.y) + (bb.x + bb.y);
    }
    __syncthreads();

    const float nj = snorm[j];
    const int   tj = stags[j];

    // ---- pairwise loss: this CTA's 16 i-rows, 4 per thread ----
    float acc = 0.0f;
    #pragma unroll
    for (int ig = 0; ig < 4; ig++) {
        const int i = chunk * KPC + (tid >> 6) + ig * 4;
        const ulonglong2* rowi = (const ulonglong2*)erow[i];   // warp-broadcast
        unsigned long long s01 = 0ull, s23 = 0ull;
        #pragma unroll
        for (int d4 = 0; d4 < D / 4; d4++) {
            ulonglong2 v = rowi[d4];
            s01 = ffma2(v.x, ejp[2 * d4 + 0], s01);
            s23 = ffma2(v.y, ejp[2 * d4 + 1], s23);
        }
        float2 a = unpack2(s01), bb = unpack2(s23);
        float s = (a.x + a.y) + (bb.x + bb.y);

        float expo = (snorm[i] + nj - 2.0f * s) * (1.0f / (float)D);
        float pred = 2.0f / (1.0f + __expf(expo));
        float ts   = (stags[i] == tj) ? 1.0f : 0.0f;
        float dd   = pred - ts;
        acc = fmaf(dd, dd, acc);
    }

    // ---- reduction: warp shuffles, then warp leaders ----
    #pragma unroll
    for (int o = 16; o > 0; o >>= 1)
        acc += __shfl_down_sync(0xFFFFFFFFu, acc, o);
    if ((tid & 31) == 0) swarp[tid >> 5] = acc;
    __syncthreads();
    if (tid == 0) {
        float v = 0.0f;
        #pragma unroll
        for (int w = 0; w < THREADS / 32; w++) v += swarp[w];
        g_partial[cta] = v;
        __threadfence();
        unsigned old = atomicAdd(&g_done, 1u);
        s_last = (old == GRID - 1);
    }
    __syncthreads();

    // ---- last CTA: deterministic final reduce over 128 partials ----
    if (s_last && tid < 32) {
        float v = g_partial[tid]      + g_partial[tid + 32]
                + g_partial[tid + 64] + g_partial[tid + 96];
        #pragma unroll
        for (int o = 16; o > 0; o >>= 1)
            v += __shfl_down_sync(0xFFFFFFFFu, v, o);
        if (tid == 0) {
            g_done = 0;                   // reset for next graph replay
            out[0] = v * (1.0f / (float)(K * K * B));
        }
    }
}

extern "C" void kernel_launch(void* const* d_in, const int* in_sizes, int n_in,
                              void* d_out, int out_size)
{
    const float* ebd  = (const float*)d_in[0];   // [32,64,192,128] f32
    const float* kpts = (const float*)d_in[1];   // [32,64,2] f32
    const int*   tags = (const int*)d_in[2];     // [32,64] i32
    float* out = (float*)d_out;

    tagloss_fused_kernel<<<GRID, THREADS>>>(ebd, kpts, tags, out);
}

// round 7
// speedup vs baseline: 1.2091x; 1.0152x over previous
#include <cuda_runtime.h>
#include <math.h>

#define B 32
#define D 64
#define H 192
#define W 128
#define K 64
#define CPB 4                   // CTAs per batch = cluster size
#define GRID (B * CPB)          // 128 CTAs, single wave
#define THREADS 512
#define KPC (K / CPB)           // 16 keypoints gathered / i-rows per CTA
#define ROWPAD 68               // row stride (words): 16B-aligned

__device__ __align__(16) float g_partial[GRID];
__device__ unsigned int g_done = 0;

// ---- PTX helpers ----
__device__ __forceinline__ unsigned long long ffma2(unsigned long long a,
                                                    unsigned long long b,
                                                    unsigned long long c)
{
    unsigned long long d;
    asm("fma.rn.f32x2 %0, %1, %2, %3;" : "=l"(d) : "l"(a), "l"(b), "l"(c));
    return d;
}
__device__ __forceinline__ float2 unpack2(unsigned long long v)
{
    float x, y;
    asm("mov.b64 {%0, %1}, %2;" : "=f"(x), "=f"(y) : "l"(v));
    return make_float2(x, y);
}
__device__ __forceinline__ unsigned long long pack2(float x, float y)
{
    unsigned long long v;
    asm("mov.b64 %0, {%1, %2};" : "=l"(v) : "f"(x), "f"(y));
    return v;
}
__device__ __forceinline__ unsigned smem_u32(const void* p)
{
    unsigned a;
    asm("{ .reg .u64 t; cvta.to.shared.u64 t, %1; cvt.u32.u64 %0, t; }"
        : "=r"(a) : "l"(p));
    return a;
}
__device__ __forceinline__ unsigned mapa_u32(unsigned addr, unsigned rank)
{
    unsigned r;
    asm("mapa.shared::cluster.u32 %0, %1, %2;" : "=r"(r) : "r"(addr), "r"(rank));
    return r;
}
__device__ __forceinline__ void st_cluster_f64(unsigned addr, unsigned long long v)
{
    asm volatile("st.shared::cluster.b64 [%0], %1;" :: "r"(addr), "l"(v) : "memory");
}
__device__ __forceinline__ unsigned ctarank()
{
    unsigned r;
    asm("mov.u32 %0, %%cluster_ctarank;" : "=r"(r));
    return r;
}

__global__ __launch_bounds__(THREADS, 1) __cluster_dims__(CPB, 1, 1)
void tagloss_fused_kernel(const float* __restrict__ ebd,
                          const float* __restrict__ kpts,
                          const int*   __restrict__ tags,
                          float*       __restrict__ out)
{
    const int cta   = blockIdx.x;
    const int b     = cta >> 2;
    const int chunk = (int)ctarank();
    const int tid   = threadIdx.x;

    __shared__ __align__(16) float erow[K][ROWPAD];  // all 64 rows (filled by cluster)
    __shared__ float snorm[K];
    __shared__ float swarp[THREADS / 32];
    __shared__ bool  s_last;

    // ---- early independent loads (registers, no SMEM, no sync) ----
    const int j  = tid & 63;
    const int i0 = chunk * KPC + (tid >> 6);         // first own i-row (0..7 within chunk)
    const int i1 = i0 + 8;                           // second own i-row
    const int tj  = tags[(size_t)b * K + j];
    const int ti0 = tags[(size_t)b * K + i0];
    const int ti1 = tags[(size_t)b * K + i1];

    // ---- own gather element: keypoint kl = tid>>5, d-pair = tid&31 ----
    const int kl    = tid >> 5;                      // 0..15 (local keypoint)
    const int dpair = tid & 31;                      // d = 2*dpair
    float2 rc = ((const float2*)kpts)[(size_t)b * K + chunk * KPC + kl]; // 1 line/CTA
    const int r = (int)floorf(rc.x * (float)H);
    const int c = (int)floorf(rc.y * (float)W);

    const float* eb = ebd + (size_t)b * D * H * W + (size_t)r * W + c;
    float v0 = eb[(size_t)(2 * dpair)     * (H * W)];
    float v1 = eb[(size_t)(2 * dpair + 1) * (H * W)];
    unsigned long long vp = pack2(v0, v1);

    // ---- broadcast into all 4 cluster CTAs' SMEM (4x 8B DSMEM stores) ----
    {
        unsigned laddr = smem_u32(&erow[chunk * KPC + kl][2 * dpair]);
        #pragma unroll
        for (unsigned rk = 0; rk < CPB; rk++)
            st_cluster_f64(mapa_u32(laddr, rk), vp);
    }
    asm volatile("barrier.cluster.arrive.aligned;" ::: "memory");
    asm volatile("barrier.cluster.wait.aligned;"   ::: "memory");

    // ---- hoist own column j (packed f32x2) + norm ----
    unsigned long long ejp[D / 2];
    {
        const ulonglong2* myrow = (const ulonglong2*)erow[j];
        #pragma unroll
        for (int d4 = 0; d4 < D / 4; d4++) {
            ulonglong2 t = myrow[d4];
            ejp[2 * d4 + 0] = t.x;
            ejp[2 * d4 + 1] = t.y;
        }
    }
    float nj;
    {
        unsigned long long s01 = 0ull, s23 = 0ull;
        #pragma unroll
        for (int d4 = 0; d4 < D / 4; d4++) {
            s01 = ffma2(ejp[2 * d4 + 0], ejp[2 * d4 + 0], s01);
            s23 = ffma2(ejp[2 * d4 + 1], ejp[2 * d4 + 1], s23);
        }
        float2 a = unpack2(s01), bb = unpack2(s23);
        nj = (a.x + a.y) + (bb.x + bb.y);
    }
    if (tid < K) snorm[tid] = nj;        // thread tid<64 has j==tid
    __syncthreads();

    // ---- pairwise loss: 2 i-rows per thread ----
    float acc = 0.0f;
    #pragma unroll
    for (int ig = 0; ig < 2; ig++) {
        const int i  = ig ? i1 : i0;
        const int ti = ig ? ti1 : ti0;
        const ulonglong2* rowi = (const ulonglong2*)erow[i];   // warp-broadcast LDS.128
        unsigned long long s01 = 0ull, s23 = 0ull;
        #pragma unroll
        for (int d4 = 0; d4 < D / 4; d4++) {
            ulonglong2 v = rowi[d4];
            s01 = ffma2(v.x, ejp[2 * d4 + 0], s01);
            s23 = ffma2(v.y, ejp[2 * d4 + 1], s23);
        }
        float2 a = unpack2(s01), bb = unpack2(s23);
        float s = (a.x + a.y) + (bb.x + bb.y);

        float expo = (snorm[i] + nj - 2.0f * s) * (1.0f / (float)D);
        float pred = __fdividef(2.0f, 1.0f + __expf(expo));
        float ts   = (ti == tj) ? 1.0f : 0.0f;
        float dd   = pred - ts;
        acc = fmaf(dd, dd, acc);
    }

    // ---- CTA reduction: warp shuffles, then warp leaders ----
    #pragma unroll
    for (int o = 16; o > 0; o >>= 1)
        acc += __shfl_down_sync(0xFFFFFFFFu, acc, o);
    if ((tid & 31) == 0) swarp[tid >> 5] = acc;
    __syncthreads();
    if (tid == 0) {
        float v = 0.0f;
        #pragma unroll
        for (int w = 0; w < THREADS / 32; w++) v += swarp[w];
        g_partial[cta] = v;
        unsigned old;
        asm volatile("atom.acq_rel.gpu.global.add.u32 %0, [%1], 1;"
                     : "=r"(old) : "l"(&g_done) : "memory");
        s_last = (old == GRID - 1);
    }
    __syncthreads();

    // ---- last CTA: deterministic final reduce over 128 partials ----
    if (s_last && tid < 32) {
        float4 p = ((const float4*)g_partial)[tid];   // 32 lanes x 4 = 128
        float v = (p.x + p.y) + (p.z + p.w);
        #pragma unroll
        for (int o = 16; o > 0; o >>= 1)
            v += __shfl_down_sync(0xFFFFFFFFu, v, o);
        if (tid == 0) {
            g_done = 0;                   // reset for next graph replay
            out[0] = v * (1.0f / (float)(K * K * B));
        }
    }
}

extern "C" void kernel_launch(void* const* d_in, const int* in_sizes, int n_in,
                              void* d_out, int out_size)
{
    const float* ebd  = (const float*)d_in[0];   // [32,64,192,128] f32
    const float* kpts = (const float*)d_in[1];   // [32,64,2] f32
    const int*   tags = (const int*)d_in[2];     // [32,64] i32
    float* out = (float*)d_out;

    tagloss_fused_kernel<<<GRID, THREADS>>>(ebd, kpts, tags, out);
}